// round 2
// baseline (speedup 1.0000x reference)
#include <cuda_runtime.h>

// ---------------------------------------------------------------------------
// Fused dopri5 neural-ODE integrator, fp32 SIMT baseline.
//   x:[4096,256], W1/W2:[256,256], 40 steps x 6 stages, f(x)=tanh(x@W1)@W2
// Each CTA owns RTILE=16 rows for the whole integration:
//   - x (and final accumulator) live in registers (4 x float4 / thread)
//   - k1..k5 in smem (k6 reuses k2's slot; k2 is dead for the final combo)
//   - stage input xs and tanh intermediate hb in smem (padded lda=260)
//   - W streamed global->smem via cp.async, double-buffered 32-row tiles
// ---------------------------------------------------------------------------

#define NSTEPS  40
#define HSTEP   0.025f
#define DIMD    256
#define RTILE   16
#define LDA     260          // padded row stride for xs/hb (floats)
#define KT      32           // k-dim tile rows per W smem tile
#define NT      (DIMD / KT)  // 8 tiles per GEMM
#define THREADS 256

#define WBUF_F (2 * KT * DIMD)        // 16384 floats (double-buffered W tile)
#define KS_F   (5 * RTILE * DIMD)     // 20480 floats (k slots)
#define XS_F   (RTILE * LDA)          // 4160 floats
#define SMEM_FLOATS (WBUF_F + KS_F + 2 * XS_F)
#define SMEM_BYTES  (SMEM_FLOATS * 4) // 180736 B

// ---------------- cp.async helpers ----------------
__device__ __forceinline__ void cp_async16(void* sdst, const void* gsrc) {
    unsigned s = (unsigned)__cvta_generic_to_shared(sdst);
    asm volatile("cp.async.cg.shared.global [%0], [%1], 16;\n" ::"r"(s), "l"(gsrc));
}
__device__ __forceinline__ void cp_commit() {
    asm volatile("cp.async.commit_group;\n");
}
__device__ __forceinline__ void cp_wait0() {
    asm volatile("cp.async.wait_group 0;\n");
}

// precise-enough tanh (~1e-7 rel): immune to -use_fast_math tanhf approx
__device__ __forceinline__ float fast_tanh(float x) {
    float ax = fabsf(x);
    float e  = __expf(2.0f * ax);          // inf for large ax -> t = 1 exactly
    float t  = 1.0f - 2.0f / (e + 1.0f);
    return copysignf(t, x);
}

__device__ __forceinline__ float4 f4fma(float c, float4 a, float4 b) {
    return make_float4(fmaf(c, a.x, b.x), fmaf(c, a.y, b.y),
                       fmaf(c, a.z, b.z), fmaf(c, a.w, b.w));
}

// ---------------------------------------------------------------------------
// C[16 x 256] = A[16 x 256 (lda=260, smem)] x W[256 x 256 (global, row-major)]
// Per-thread tile: 4 rows x 4 cols. Thread map:
//   row0 = (lane&3)*4            (4 row-groups -> W smem reads broadcast x4)
//   col0 = (warp*8 + lane>>2)*4  (64 col-groups)
// W tiles staged via cp.async double buffer; one __syncthreads per tile.
// ---------------------------------------------------------------------------
__device__ __forceinline__ void gemm16x256(const float* __restrict__ A,
                                           const float* __restrict__ Wg,
                                           float* __restrict__ wbuf,
                                           int row0, int col0, int t,
                                           float acc[4][4]) {
#pragma unroll
    for (int r = 0; r < 4; r++)
#pragma unroll
        for (int c = 0; c < 4; c++) acc[r][c] = 0.0f;

    // prefetch tile 0
#pragma unroll
    for (int i = 0; i < 8; i++) {
        int e4 = (t + i * THREADS) * 4;
        cp_async16(&wbuf[e4], Wg + e4);
    }
    cp_commit();

#pragma unroll 1
    for (int kt = 0; kt < NT; kt++) {
        cp_wait0();
        __syncthreads();   // tile kt visible; all threads done with tile kt-1
        if (kt + 1 < NT) { // prefetch next tile into the other buffer
            const float* src = Wg + (kt + 1) * KT * DIMD;
            float* dst = wbuf + ((kt + 1) & 1) * KT * DIMD;
#pragma unroll
            for (int i = 0; i < 8; i++) {
                int e4 = (t + i * THREADS) * 4;
                cp_async16(&dst[e4], src + e4);
            }
            cp_commit();
        }
        const float* wb = wbuf + (kt & 1) * KT * DIMD;
        const float* Ab = A + kt * KT;
#pragma unroll 4
        for (int kk = 0; kk < KT; kk += 4) {
            float av[4][4];
#pragma unroll
            for (int r = 0; r < 4; r++) {
                float4 a = *(const float4*)&Ab[(row0 + r) * LDA + kk];
                av[r][0] = a.x; av[r][1] = a.y; av[r][2] = a.z; av[r][3] = a.w;
            }
#pragma unroll
            for (int j = 0; j < 4; j++) {
                float4 wv = *(const float4*)&wb[(kk + j) * DIMD + col0];
#pragma unroll
                for (int r = 0; r < 4; r++) {
                    acc[r][0] = fmaf(av[r][j], wv.x, acc[r][0]);
                    acc[r][1] = fmaf(av[r][j], wv.y, acc[r][1]);
                    acc[r][2] = fmaf(av[r][j], wv.z, acc[r][2]);
                    acc[r][3] = fmaf(av[r][j], wv.w, acc[r][3]);
                }
            }
        }
    }
}

__global__ void __launch_bounds__(THREADS, 1)
ode_dopri5_kernel(const float* __restrict__ x0, const float* __restrict__ W1,
                  const float* __restrict__ W2, float* __restrict__ out) {
    extern __shared__ float smem[];
    float* wbuf = smem;               // [2][KT][256]
    float* ks   = smem + WBUF_F;      // [5][16][256]  (slot1 reused for k6)
    float* xs   = ks + KS_F;          // [16][260] stage input
    float* hb   = xs + XS_F;          // [16][260] tanh intermediate

    const int t    = threadIdx.x;
    const int lane = t & 31;
    const int wrp  = t >> 5;
    const int row0 = (lane & 3) * 4;
    const int col0 = (wrp * 8 + (lane >> 2)) * 4;
    const int gr0  = blockIdx.x * RTILE;

    // load x slab: registers (elementwise layout) + xs (stage-1 input)
    float4 xr[4];
#pragma unroll
    for (int i = 0; i < 4; i++) {
        int idx = t + i * THREADS;       // float4 index in [0,1024)
        int row = idx >> 6, c4 = idx & 63;
        float4 v = *(const float4*)&x0[(gr0 + row) * DIMD + c4 * 4];
        xr[i] = v;
        *(float4*)&xs[row * LDA + c4 * 4] = v;
    }
    // (first gemm's internal sync orders these xs writes before reads)

    const float h = HSTEP;
    const float A21 = 0.2f;
    const float A31 = (float)(3.0 / 40.0),      A32 = (float)(9.0 / 40.0);
    const float A41 = (float)(44.0 / 45.0),     A42 = (float)(-56.0 / 15.0);
    const float A43 = (float)(32.0 / 9.0);
    const float A51 = (float)(19372.0 / 6561.0), A52 = (float)(-25360.0 / 2187.0);
    const float A53 = (float)(64448.0 / 6561.0), A54 = (float)(-212.0 / 729.0);
    const float A61 = (float)(9017.0 / 3168.0),  A62 = (float)(-355.0 / 33.0);
    const float A63 = (float)(46732.0 / 5247.0), A64 = (float)(49.0 / 176.0);
    const float A65 = (float)(-5103.0 / 18656.0);
    const float B1 = (float)(35.0 / 384.0),   B3 = (float)(500.0 / 1113.0);
    const float B4 = (float)(125.0 / 192.0),  B5 = (float)(-2187.0 / 6784.0);
    const float B6 = (float)(11.0 / 84.0);

#pragma unroll 1
    for (int step = 0; step < NSTEPS; step++) {
#pragma unroll 1
        for (int s = 0; s < 6; s++) {
            float acc[4][4];

            // GEMM1 + tanh epilogue -> hb
            gemm16x256(xs, W1, wbuf, row0, col0, t, acc);
#pragma unroll
            for (int r = 0; r < 4; r++) {
                float4 v;
                v.x = fast_tanh(acc[r][0]);
                v.y = fast_tanh(acc[r][1]);
                v.z = fast_tanh(acc[r][2]);
                v.w = fast_tanh(acc[r][3]);
                *(float4*)&hb[(row0 + r) * LDA + col0] = v;
            }

            // GEMM2 -> k slot (k6 -> slot 1, k2's slot is dead by then)
            gemm16x256(hb, W2, wbuf, row0, col0, t, acc);
            const int slot = (s == 5) ? 1 : s;
            float* kd = ks + slot * (RTILE * DIMD);
#pragma unroll
            for (int r = 0; r < 4; r++) {
                float4 v = make_float4(acc[r][0], acc[r][1], acc[r][2], acc[r][3]);
                *(float4*)&kd[(row0 + r) * DIMD + col0] = v;
            }
            __syncthreads();  // k slot visible to all before elementwise reads

            // elementwise: build next stage input (or final x update)
#pragma unroll
            for (int i = 0; i < 4; i++) {
                int idx = t + i * THREADS;
                int row = idx >> 6, c4 = idx & 63;
                const float4* K0 = (const float4*)&ks[0 * RTILE * DIMD] + idx;
                const float4* K1 = (const float4*)&ks[1 * RTILE * DIMD] + idx;
                const float4* K2 = (const float4*)&ks[2 * RTILE * DIMD] + idx;
                const float4* K3 = (const float4*)&ks[3 * RTILE * DIMD] + idx;
                const float4* K4 = (const float4*)&ks[4 * RTILE * DIMD] + idx;
                float4 x = xr[i];
                float4 o;
                if (s == 0) {
                    o = f4fma(h * A21, *K0, x);
                } else if (s == 1) {
                    o = f4fma(h * A32, *K1, f4fma(h * A31, *K0, x));
                } else if (s == 2) {
                    o = f4fma(h * A43, *K2,
                        f4fma(h * A42, *K1, f4fma(h * A41, *K0, x)));
                } else if (s == 3) {
                    o = f4fma(h * A54, *K3, f4fma(h * A53, *K2,
                        f4fma(h * A52, *K1, f4fma(h * A51, *K0, x))));
                } else if (s == 4) {
                    o = f4fma(h * A65, *K4, f4fma(h * A64, *K3,
                        f4fma(h * A63, *K2, f4fma(h * A62, *K1,
                        f4fma(h * A61, *K0, x)))));
                } else {  // s == 5: final combo; K1 holds k6
                    o = f4fma(h * B6, *K1, f4fma(h * B5, *K4,
                        f4fma(h * B4, *K3, f4fma(h * B3, *K2,
                        f4fma(h * B1, *K0, x)))));
                    xr[i] = o;  // new x
                }
                *(float4*)&xs[row * LDA + c4 * 4] = o;  // stage input / next-step x
            }
            // next gemm's first internal sync orders xs writes before reads
        }
    }

    // final x -> out
#pragma unroll
    for (int i = 0; i < 4; i++) {
        int idx = t + i * THREADS;
        int row = idx >> 6, c4 = idx & 63;
        *(float4*)&out[(gr0 + row) * DIMD + c4 * 4] = xr[i];
    }
}

extern "C" void kernel_launch(void* const* d_in, const int* in_sizes, int n_in,
                              void* d_out, int out_size) {
    (void)in_sizes; (void)n_in; (void)out_size;
    const float* x0 = (const float*)d_in[0];
    const float* W1 = (const float*)d_in[1];
    const float* W2 = (const float*)d_in[2];
    float* out = (float*)d_out;

    cudaFuncSetAttribute(ode_dopri5_kernel,
                         cudaFuncAttributeMaxDynamicSharedMemorySize, SMEM_BYTES);
    ode_dopri5_kernel<<<4096 / RTILE, THREADS, SMEM_BYTES>>>(x0, W1, W2, out);
}